// round 7
// baseline (speedup 1.0000x reference)
#include <cuda_runtime.h>
#include <cuda_pipeline.h>
#include <cstdint>
#include <math.h>

#define NVARS 1024
#define BATCH 64
#define KDIM  32
#define NIN   768
#define SWEEPS 10
#define PI_F 3.14159274101257324f

// ---------------- persistent scratch (no runtime allocation) ----------------
__device__ float V_g[BATCH * NVARS * KDIM];     // 8 MB
__device__ float v0_g[BATCH * KDIM];
__device__ unsigned short list_g[BATCH * NVARS];
__device__ int cnt_g[BATCH];

// ---------------- f32x2 helpers ----------------
__device__ __forceinline__ void ffma2(unsigned long long &d, unsigned long long a,
                                      unsigned long long b) {
    asm("fma.rn.f32x2 %0, %1, %2, %3;" : "=l"(d) : "l"(a), "l"(b), "l"(d));
}
__device__ __forceinline__ void fadd2(unsigned long long &d, unsigned long long a,
                                      unsigned long long b) {
    asm("add.rn.f32x2 %0, %1, %2;" : "=l"(d) : "l"(a), "l"(b));
}
__device__ __forceinline__ unsigned long long pk2(float lo, float hi) {
    unsigned long long r;
    asm("mov.b64 %0, {%1, %2};" : "=l"(r) : "f"(lo), "f"(hi));
    return r;
}
__device__ __forceinline__ void up2(unsigned long long v, float &lo, float &hi) {
    asm("mov.b64 {%0, %1}, %2;" : "=f"(lo), "=f"(hi) : "l"(v));
}

// ---------------- threefry2x32 core, exact JAX schedule ----------------
__device__ __forceinline__ void tf2x32(unsigned k0, unsigned k1,
                                       unsigned x0, unsigned x1,
                                       unsigned &y0, unsigned &y1) {
    unsigned ks2 = k0 ^ k1 ^ 0x1BD11BDAu;
    x0 += k0; x1 += k1;
#define TFR(r) { x0 += x1; x1 = (x1 << r) | (x1 >> (32 - r)); x1 ^= x0; }
    TFR(13) TFR(15) TFR(26) TFR(6)  x0 += k1;  x1 += ks2 + 1u;
    TFR(17) TFR(29) TFR(16) TFR(24) x0 += ks2; x1 += k0 + 2u;
    TFR(13) TFR(15) TFR(26) TFR(6)  x0 += k0;  x1 += k1 + 3u;
    TFR(17) TFR(29) TFR(16) TFR(24) x0 += k1;  x1 += ks2 + 4u;
    TFR(13) TFR(15) TFR(26) TFR(6)  x0 += ks2; x1 += k0 + 5u;
#undef TFR
    y0 = x0; y1 = x1;
}

// PARTITIONABLE threefry (modern JAX default)
__device__ __forceinline__ void derive_keys(unsigned &k1a, unsigned &k1b,
                                            unsigned &k2a, unsigned &k2b) {
    tf2x32(0u, 42u, 0u, 0u, k1a, k1b);   // subkey 0
    tf2x32(0u, 42u, 0u, 1u, k2a, k2b);   // subkey 1
}

__device__ __forceinline__ unsigned tf_bits(unsigned ka, unsigned kb, unsigned e) {
    unsigned y0, y1;
    tf2x32(ka, kb, 0u, e, y0, y1);
    return y0 ^ y1;
}

// bits -> N(0,1): uniform(nextafter(-1,0), 1) then sqrt(2)*erfinv (XLA f32 path)
__device__ __forceinline__ float bits_to_normal(unsigned bits) {
    float u01 = __fadd_rn(__uint_as_float((bits >> 9) | 0x3F800000u), -1.0f);
    float u = __fadd_rn(__fmul_rn(u01, 2.0f), -0.99999994f);
    u = fmaxf(u, -0.99999994f);
    float x = u;
    float xx = __fmul_rn(x, x);
    float w = -log1pf(-xx);
    float p;
    if (w < 5.0f) {
        w = __fadd_rn(w, -2.5f);
        p = 2.81022636e-08f;
        p = __fadd_rn(__fmul_rn(p, w), 3.43273939e-07f);
        p = __fadd_rn(__fmul_rn(p, w), -3.5233877e-06f);
        p = __fadd_rn(__fmul_rn(p, w), -4.39150654e-06f);
        p = __fadd_rn(__fmul_rn(p, w), 0.00021858087f);
        p = __fadd_rn(__fmul_rn(p, w), -0.00125372503f);
        p = __fadd_rn(__fmul_rn(p, w), -0.00417768164f);
        p = __fadd_rn(__fmul_rn(p, w), 0.246640727f);
        p = __fadd_rn(__fmul_rn(p, w), 1.50140941f);
    } else {
        w = __fadd_rn(sqrtf(w), -3.0f);
        p = -0.000200214257f;
        p = __fadd_rn(__fmul_rn(p, w), 0.000100950558f);
        p = __fadd_rn(__fmul_rn(p, w), 0.00134934322f);
        p = __fadd_rn(__fmul_rn(p, w), -0.00367342844f);
        p = __fadd_rn(__fmul_rn(p, w), 0.00573950773f);
        p = __fadd_rn(__fmul_rn(p, w), -0.0076224613f);
        p = __fadd_rn(__fmul_rn(p, w), 0.00943887047f);
        p = __fadd_rn(__fmul_rn(p, w), 1.00167406f);
        p = __fadd_rn(__fmul_rn(p, w), 2.83297682f);
    }
    return __fmul_rn(1.41421354f, __fmul_rn(p, x));
}

__device__ __forceinline__ float warp_sum(float v) {
#pragma unroll
    for (int off = 16; off; off >>= 1)
        v += __shfl_xor_sync(0xffffffffu, v, off);
    return v;
}

// ---------------- kernel A: v0 (one warp per batch) ----------------
__global__ void v0_kernel() {
    int b = blockIdx.x;
    int l = threadIdx.x;
    unsigned k1a, k1b, k2a, k2b; derive_keys(k1a, k1b, k2a, k2b);
    unsigned e = (unsigned)(b * 32 + l);
    float n = bits_to_normal(tf_bits(k1a, k1b, e));
    float ss = warp_sum(__fmul_rn(n, n));
    v0_g[b * 32 + l] = n / sqrtf(ss);
}

// ---------------- kernel B: V init (one warp per (b,n)) ----------------
__global__ void initV_kernel(const float* __restrict__ z,
                             const int* __restrict__ is_input) {
    int gw = (blockIdx.x * blockDim.x + threadIdx.x) >> 5;
    int l = threadIdx.x & 31;
    int b = gw >> 10, n = gw & 1023;
    unsigned k1a, k1b, k2a, k2b; derive_keys(k1a, k1b, k2a, k2b);

    float v0l = v0_g[b * 32 + l];
    unsigned e = (unsigned)gw * 32u + (unsigned)l;
    float r = bits_to_normal(tf_bits(k2a, k2b, e));

    float d = warp_sum(__fmul_rn(r, v0l));
    float rp = __fadd_rn(r, -__fmul_rn(d, v0l));
    float nr = sqrtf(warp_sum(__fmul_rn(rp, rp)));
    float R = rp / nr;

    float zf; int ii;
    if (n == 0)        { zf = 1.0f; ii = 1; }
    else if (n <= NIN) { zf = z[b * NIN + n - 1]; ii = is_input[b * NIN + n - 1]; }
    else               { zf = 0.0f; ii = 0; }

    float V;
    if (ii > 0) {
        float x = __fmul_rn(PI_F, zf);
        V = __fadd_rn(__fmul_rn(-cosf(x), v0l), __fmul_rn(sinf(x), R));
    } else {
        V = R;
    }
    if (n == 0) V = v0l;
    V_g[gw * 32 + l] = V;
}

// ---------------- kernel C: per-batch free list (one warp per batch) ----------------
__global__ void freelist_kernel(const int* __restrict__ is_input) {
    int b = blockIdx.x;
    int l = threadIdx.x;
    int m = 0;
    for (int base = 1; base < 1024; base += 32) {
        int n = base + l;
        bool f = (n < 1024) && (n > NIN || is_input[b * NIN + n - 1] == 0);
        unsigned msk = __ballot_sync(0xffffffffu, f);
        if (f) {
            int pos = m + __popc(msk & ((1u << l) - 1u));
            list_g[b * 1024 + pos] = (unsigned short)n;
        }
        m += __popc(msk);
    }
    if (l == 0) cnt_g[b] = m;
}

// ---------------- kernel D: pipelined mixing solve (one CTA per batch) ----------------
// 17 warps: warps 0..15 = dot warps (warp w owns rows [64w,64w+64), lane l = col l),
// warp 16 = reducer.
// C rows are staged 3-deep into a 4-slot smem ring via cp.async; all coupling
// scalars C[i_{m+1}, i_m] precomputed once into sv[] (C is symmetric).
__global__ void __launch_bounds__(544, 1)
mix_kernel(const float* __restrict__ C,
           const float* __restrict__ z,
           const int* __restrict__ is_input,
           float* __restrict__ out) {
    const int b = blockIdx.x;
    const int tid = threadIdx.x;
    const int w = tid >> 5;
    const int l = tid & 31;
    const bool dotw = (w < 16);

    __shared__ __align__(16) float cbuf[4][NVARS];   // 16 KB C-row ring
    __shared__ float pT[2][16 * 32];
    __shared__ float vnbuf[2][32];
    __shared__ float sv[NVARS];                      // coupling scalars
    __shared__ unsigned short lst[NVARS];
    __shared__ int scnt;

    for (int idx = tid; idx < 1024; idx += 544)
        lst[idx] = list_g[b * 1024 + idx];
    if (tid == 0) scnt = cnt_g[b];
    __syncthreads();
    const int cnt = scnt;
    const int total = cnt * SWEEPS;

    // coupling scalars: sv[m] = C[lst[(m+1)%cnt], lst[m]]  (symmetric C)
    for (int m = tid; m < cnt; m += 544) {
        int ia = lst[m];
        int ib = lst[(m + 1 < cnt) ? m + 1 : 0];
        sv[m] = __ldg(C + (size_t)ib * NVARS + ia);
    }

    unsigned long long v2[32];
    if (dotw) {
#pragma unroll
        for (int p = 0; p < 32; p++) {
            int row = w * 64 + 2 * p;
            v2[p] = pk2(V_g[(b * 1024 + row) * 32 + l],
                        V_g[(b * 1024 + row + 1) * 32 + l]);
        }
    }
    __syncthreads();

    // index pipeline
    int i_cur = lst[0];
    int i_n1 = lst[1 % cnt];
    int i_n2 = lst[2 % cnt];
    int p3 = 3 % cnt;
    int i_n3 = lst[p3];
    int i_prev = -1;
    int mt = 0;

    // prologue staging: rows i_1 -> cbuf[1], i_2 -> cbuf[2]
    if (tid < 256)
        __pipeline_memcpy_async(&cbuf[1][tid * 4],
                                C + (size_t)i_n1 * NVARS + tid * 4, 16);
    __pipeline_commit();
    if (tid < 256)
        __pipeline_memcpy_async(&cbuf[2][tid * 4],
                                C + (size_t)i_n2 * NVARS + tid * 4, 16);
    __pipeline_commit();

    // prologue: full dot for i_0 from gmem
    if (dotw) {
        const ulonglong2* Cp = reinterpret_cast<const ulonglong2*>(
            C + (size_t)i_cur * NVARS + w * 64);
        unsigned long long a0 = 0ull, a1 = 0ull, a2 = 0ull, a3 = 0ull;
#pragma unroll
        for (int q = 0; q < 16; q++) {
            ulonglong2 cc = Cp[q];
            ffma2(((q & 1) ? a2 : a0), cc.x, v2[2 * q]);
            ffma2(((q & 1) ? a3 : a1), cc.y, v2[2 * q + 1]);
        }
        fadd2(a0, a0, a2); fadd2(a1, a1, a3); fadd2(a0, a0, a1);
        float x, y; up2(a0, x, y);
        pT[0][w * 32 + l] = x + y;
    }
    __pipeline_wait_prior(1);        // row i_1 landed
    __syncthreads();

    float vn_prev = 0.0f;            // reducer state
    float s_corr = 0.0f;

    for (int t = 0; t < total; t++) {
        const int rd = t & 1, wr = (t + 1) & 1;

        // stage row i_{t+3} into ring slot (t+3)&3
        if (tid < 256)
            __pipeline_memcpy_async(&cbuf[(t + 3) & 3][tid * 4],
                                    C + (size_t)i_n3 * NVARS + tid * 4, 16);
        __pipeline_commit();

        if (dotw) {
            float s_b = sv[mt];                      // C[i_{t+1}, i_t]
            // apply vn_{t-1} to row i_{t-1} (owner only)
            if (t > 0 && w == (i_prev >> 6)) {
                float vnp = vnbuf[wr][l];            // wr == (t-1)&1
                int j = i_prev & 63, pp = j >> 1;
#pragma unroll
                for (int p = 0; p < 32; p++)
                    if (p == pp) {
                        float x, y; up2(v2[p], x, y);
                        if (j & 1) y = vnp; else x = vnp;
                        v2[p] = pk2(x, y);
                    }
            }
            // dot for i_{t+1} from staged smem row
            const ulonglong2* Cs = reinterpret_cast<const ulonglong2*>(
                &cbuf[(t + 1) & 3][w * 64]);
            unsigned long long a0 = 0ull, a1 = 0ull, a2 = 0ull, a3 = 0ull;
#pragma unroll
            for (int q = 0; q < 16; q++) {
                ulonglong2 cc = Cs[q];
                ffma2(((q & 1) ? a2 : a0), cc.x, v2[2 * q]);
                ffma2(((q & 1) ? a3 : a1), cc.y, v2[2 * q + 1]);
            }
            fadd2(a0, a0, a2); fadd2(a1, a1, a3); fadd2(a0, a0, a1);
            float x, y; up2(a0, x, y);
            float partial = x + y;
            // exclusion of in-flight row i_t (owner only, pre-update value)
            if (w == (i_cur >> 6)) {
                int j = i_cur & 63, pp = j >> 1;
                float vold = 0.0f;
#pragma unroll
                for (int p = 0; p < 32; p++)
                    if (p == pp) {
                        float xx, yy; up2(v2[p], xx, yy);
                        vold = (j & 1) ? yy : xx;
                    }
                partial = fmaf(-s_b, vold, partial);
            }
            pT[wr][w * 32 + l] = partial;
        } else if (w == 16) {
            float s_next = sv[mt];                   // carried to t+1
            // reducer: g(i_t)
            float t0 = pT[rd][0 * 32 + l],  t1 = pT[rd][1 * 32 + l];
            float t2 = pT[rd][2 * 32 + l],  t3 = pT[rd][3 * 32 + l];
            float t4 = pT[rd][4 * 32 + l],  t5 = pT[rd][5 * 32 + l];
            float t6 = pT[rd][6 * 32 + l],  t7 = pT[rd][7 * 32 + l];
            float t8 = pT[rd][8 * 32 + l],  t9 = pT[rd][9 * 32 + l];
            float ta = pT[rd][10 * 32 + l], tb = pT[rd][11 * 32 + l];
            float tc = pT[rd][12 * 32 + l], td = pT[rd][13 * 32 + l];
            float te = pT[rd][14 * 32 + l], tf = pT[rd][15 * 32 + l];
            float g = (((t0 + t1) + (t2 + t3)) + ((t4 + t5) + (t6 + t7)))
                    + (((t8 + t9) + (ta + tb)) + ((tc + td) + (te + tf)));
            g = fmaf(s_corr, vn_prev, g);
            float ss = warp_sum(g * g);
            ss = fmaxf(ss, 1e-24f);
            float vn = -g * rsqrtf(ss);
            vnbuf[rd][l] = vn;
            vn_prev = vn;
            s_corr = s_next;
        }

        __pipeline_wait_prior(1);
        __syncthreads();

        i_prev = i_cur; i_cur = i_n1; i_n1 = i_n2; i_n2 = i_n3;
        p3++; if (p3 >= cnt) p3 = 0;
        i_n3 = lst[p3];
        mt++; if (mt >= cnt) mt = 0;
    }

    // final update: vn_{total-1}
    if (dotw && total > 0 && w == (i_prev >> 6)) {
        float vnp = vnbuf[(total - 1) & 1][l];
        int j = i_prev & 63, pp = j >> 1;
#pragma unroll
        for (int p = 0; p < 32; p++)
            if (p == pp) {
                float x, y; up2(v2[p], x, y);
                if (j & 1) y = vnp; else x = vnp;
                v2[p] = pk2(x, y);
            }
    }

    // ---------------- epilogue: z_out[:, 1:769] ----------------
    if (dotw) {
        float v0l = v0_g[b * 32 + l];
        const float CLO = (float)(-1.0 + 1e-7);
        const float CHI = (float)( 1.0 - 1e-7);
#pragma unroll
        for (int j = 0; j < 64; j++) {
            int n = w * 64 + j;
            if (n >= 1 && n <= NIN) {
                float x, y; up2(v2[j >> 1], x, y);
                float Vv = (j & 1) ? y : x;
                float d = warp_sum(__fmul_rn(Vv, v0l));
                if (l == 0) {
                    int idx = b * NIN + n - 1;
                    float res;
                    if (is_input[idx] != 0) {
                        res = z[idx];
                    } else {
                        float ca = fminf(fmaxf(-d, CLO), CHI);
                        res = acosf(ca) / PI_F;
                    }
                    out[idx] = res;
                }
            }
        }
    }
}

// ---------------- launcher ----------------
extern "C" void kernel_launch(void* const* d_in, const int* in_sizes, int n_in,
                              void* d_out, int out_size) {
    const float* C        = (const float*)d_in[0];
    const float* z        = (const float*)d_in[1];
    const int*   is_input = (const int*)d_in[2];
    float* out = (float*)d_out;

    v0_kernel<<<BATCH, 32>>>();
    initV_kernel<<<(BATCH * NVARS) / 8, 256>>>(z, is_input);
    freelist_kernel<<<BATCH, 32>>>(is_input);
    mix_kernel<<<BATCH, 544>>>(C, z, is_input, out);
}

// round 8
// speedup vs baseline: 1.3911x; 1.3911x over previous
#include <cuda_runtime.h>
#include <cuda_pipeline.h>
#include <cstdint>
#include <math.h>

#define NVARS 1024
#define BATCH 64
#define KDIM  32
#define NIN   768
#define SWEEPS 10
#define PI_F 3.14159274101257324f

// dynamic smem layout (floats)
#define F_CBUF 0            // 12 rows * 1024  (3-group cp.async ring)
#define F_SVD  12288        // 7 * 1024 coupling-scalar tables
#define F_PT   19456        // 2 * 4 * 512 partials
#define F_VNB  23552        // 2 * 4 * 32 vn broadcast
#define F_LST  23808        // 1024 ushort = 512 floats
#define SMEM_FLOATS 24320
#define SMEM_BYTES (SMEM_FLOATS * 4)

// ---------------- persistent scratch (no runtime allocation) ----------------
__device__ float V_g[BATCH * NVARS * KDIM];     // 8 MB
__device__ float VH_g[BATCH * NVARS * KDIM];    // 8 MB value-history by list position
__device__ float v0_g[BATCH * KDIM];
__device__ unsigned short list_g[BATCH * NVARS];
__device__ int cnt_g[BATCH];

// ---------------- f32x2 helpers ----------------
__device__ __forceinline__ void ffma2(unsigned long long &d, unsigned long long a,
                                      unsigned long long b) {
    asm("fma.rn.f32x2 %0, %1, %2, %3;" : "=l"(d) : "l"(a), "l"(b), "l"(d));
}
__device__ __forceinline__ void fadd2(unsigned long long &d, unsigned long long a,
                                      unsigned long long b) {
    asm("add.rn.f32x2 %0, %1, %2;" : "=l"(d) : "l"(a), "l"(b));
}
__device__ __forceinline__ unsigned long long pk2(float lo, float hi) {
    unsigned long long r;
    asm("mov.b64 %0, {%1, %2};" : "=l"(r) : "f"(lo), "f"(hi));
    return r;
}
__device__ __forceinline__ void up2(unsigned long long v, float &lo, float &hi) {
    asm("mov.b64 {%0, %1}, %2;" : "=f"(lo), "=f"(hi) : "l"(v));
}

__device__ __forceinline__ float dot_row(const ulonglong2* __restrict__ Cp,
                                         const unsigned long long (&v2)[32]) {
    unsigned long long a0 = 0ull, a1 = 0ull, a2 = 0ull, a3 = 0ull;
#pragma unroll
    for (int q = 0; q < 16; q++) {
        ulonglong2 cc = Cp[q];
        ffma2(((q & 1) ? a2 : a0), cc.x, v2[2 * q]);
        ffma2(((q & 1) ? a3 : a1), cc.y, v2[2 * q + 1]);
    }
    fadd2(a0, a0, a2); fadd2(a1, a1, a3); fadd2(a0, a0, a1);
    float x, y; up2(a0, x, y);
    return x + y;
}

__device__ __forceinline__ void insert_elem(unsigned long long (&v2)[32], int j, float vn) {
    int p0 = j >> 1;
#pragma unroll
    for (int p = 0; p < 32; p++)
        if (p == p0) {
            float x, y; up2(v2[p], x, y);
            if (j & 1) y = vn; else x = vn;
            v2[p] = pk2(x, y);
        }
}

// ---------------- threefry2x32 core, exact JAX schedule ----------------
__device__ __forceinline__ void tf2x32(unsigned k0, unsigned k1,
                                       unsigned x0, unsigned x1,
                                       unsigned &y0, unsigned &y1) {
    unsigned ks2 = k0 ^ k1 ^ 0x1BD11BDAu;
    x0 += k0; x1 += k1;
#define TFR(r) { x0 += x1; x1 = (x1 << r) | (x1 >> (32 - r)); x1 ^= x0; }
    TFR(13) TFR(15) TFR(26) TFR(6)  x0 += k1;  x1 += ks2 + 1u;
    TFR(17) TFR(29) TFR(16) TFR(24) x0 += ks2; x1 += k0 + 2u;
    TFR(13) TFR(15) TFR(26) TFR(6)  x0 += k0;  x1 += k1 + 3u;
    TFR(17) TFR(29) TFR(16) TFR(24) x0 += k1;  x1 += ks2 + 4u;
    TFR(13) TFR(15) TFR(26) TFR(6)  x0 += ks2; x1 += k0 + 5u;
#undef TFR
    y0 = x0; y1 = x1;
}

// PARTITIONABLE threefry (modern JAX default)
__device__ __forceinline__ void derive_keys(unsigned &k1a, unsigned &k1b,
                                            unsigned &k2a, unsigned &k2b) {
    tf2x32(0u, 42u, 0u, 0u, k1a, k1b);
    tf2x32(0u, 42u, 0u, 1u, k2a, k2b);
}

__device__ __forceinline__ unsigned tf_bits(unsigned ka, unsigned kb, unsigned e) {
    unsigned y0, y1;
    tf2x32(ka, kb, 0u, e, y0, y1);
    return y0 ^ y1;
}

__device__ __forceinline__ float bits_to_normal(unsigned bits) {
    float u01 = __fadd_rn(__uint_as_float((bits >> 9) | 0x3F800000u), -1.0f);
    float u = __fadd_rn(__fmul_rn(u01, 2.0f), -0.99999994f);
    u = fmaxf(u, -0.99999994f);
    float x = u;
    float xx = __fmul_rn(x, x);
    float w = -log1pf(-xx);
    float p;
    if (w < 5.0f) {
        w = __fadd_rn(w, -2.5f);
        p = 2.81022636e-08f;
        p = __fadd_rn(__fmul_rn(p, w), 3.43273939e-07f);
        p = __fadd_rn(__fmul_rn(p, w), -3.5233877e-06f);
        p = __fadd_rn(__fmul_rn(p, w), -4.39150654e-06f);
        p = __fadd_rn(__fmul_rn(p, w), 0.00021858087f);
        p = __fadd_rn(__fmul_rn(p, w), -0.00125372503f);
        p = __fadd_rn(__fmul_rn(p, w), -0.00417768164f);
        p = __fadd_rn(__fmul_rn(p, w), 0.246640727f);
        p = __fadd_rn(__fmul_rn(p, w), 1.50140941f);
    } else {
        w = __fadd_rn(sqrtf(w), -3.0f);
        p = -0.000200214257f;
        p = __fadd_rn(__fmul_rn(p, w), 0.000100950558f);
        p = __fadd_rn(__fmul_rn(p, w), 0.00134934322f);
        p = __fadd_rn(__fmul_rn(p, w), -0.00367342844f);
        p = __fadd_rn(__fmul_rn(p, w), 0.00573950773f);
        p = __fadd_rn(__fmul_rn(p, w), -0.0076224613f);
        p = __fadd_rn(__fmul_rn(p, w), 0.00943887047f);
        p = __fadd_rn(__fmul_rn(p, w), 1.00167406f);
        p = __fadd_rn(__fmul_rn(p, w), 2.83297682f);
    }
    return __fmul_rn(1.41421354f, __fmul_rn(p, x));
}

__device__ __forceinline__ float warp_sum(float v) {
#pragma unroll
    for (int off = 16; off; off >>= 1)
        v += __shfl_xor_sync(0xffffffffu, v, off);
    return v;
}

// ---------------- init kernels ----------------
__global__ void v0_kernel() {
    int b = blockIdx.x;
    int l = threadIdx.x;
    unsigned k1a, k1b, k2a, k2b; derive_keys(k1a, k1b, k2a, k2b);
    unsigned e = (unsigned)(b * 32 + l);
    float n = bits_to_normal(tf_bits(k1a, k1b, e));
    float ss = warp_sum(__fmul_rn(n, n));
    v0_g[b * 32 + l] = n / sqrtf(ss);
}

__global__ void initV_kernel(const float* __restrict__ z,
                             const int* __restrict__ is_input) {
    int gw = (blockIdx.x * blockDim.x + threadIdx.x) >> 5;
    int l = threadIdx.x & 31;
    int b = gw >> 10, n = gw & 1023;
    unsigned k1a, k1b, k2a, k2b; derive_keys(k1a, k1b, k2a, k2b);

    float v0l = v0_g[b * 32 + l];
    unsigned e = (unsigned)gw * 32u + (unsigned)l;
    float r = bits_to_normal(tf_bits(k2a, k2b, e));

    float d = warp_sum(__fmul_rn(r, v0l));
    float rp = __fadd_rn(r, -__fmul_rn(d, v0l));
    float nr = sqrtf(warp_sum(__fmul_rn(rp, rp)));
    float R = rp / nr;

    float zf; int ii;
    if (n == 0)        { zf = 1.0f; ii = 1; }
    else if (n <= NIN) { zf = z[b * NIN + n - 1]; ii = is_input[b * NIN + n - 1]; }
    else               { zf = 0.0f; ii = 0; }

    float V;
    if (ii > 0) {
        float x = __fmul_rn(PI_F, zf);
        V = __fadd_rn(__fmul_rn(-cosf(x), v0l), __fmul_rn(sinf(x), R));
    } else {
        V = R;
    }
    if (n == 0) V = v0l;
    V_g[gw * 32 + l] = V;
}

__global__ void freelist_kernel(const int* __restrict__ is_input) {
    int b = blockIdx.x;
    int l = threadIdx.x;
    int m = 0;
    for (int base = 1; base < 1024; base += 32) {
        int n = base + l;
        bool f = (n < 1024) && (n > NIN || is_input[b * NIN + n - 1] == 0);
        unsigned msk = __ballot_sync(0xffffffffu, f);
        if (f) {
            int pos = m + __popc(msk & ((1u << l) - 1u));
            list_g[b * 1024 + pos] = (unsigned short)n;
        }
        m += __popc(msk);
    }
    if (l == 0) cnt_g[b] = m;
}

// VH[b][m][l] = V_init[b][lst[m]][l]
__global__ void vhinit_kernel() {
    int b = blockIdx.x;
    int wi = threadIdx.x >> 5;
    int l = threadIdx.x & 31;
    int c = cnt_g[b];
    for (int m = wi; m < c; m += 8) {
        int i = list_g[b * 1024 + m];
        VH_g[((size_t)b * 1024 + m) * 32 + l] = V_g[((size_t)b * 1024 + i) * 32 + l];
    }
}

// ---------------- kernel D: S=4 batched pipelined mixing solve ----------------
__global__ void __launch_bounds__(544, 1)
mix_kernel(const float* __restrict__ C,
           const float* __restrict__ z,
           const int* __restrict__ is_input,
           float* __restrict__ out) {
    extern __shared__ float sm[];
    unsigned short* lstS = (unsigned short*)&sm[F_LST];

    const int b = blockIdx.x;
    const int tid = threadIdx.x;
    const int w = tid >> 5;
    const int l = tid & 31;
    const bool dotw = (w < 16);

    __shared__ int scnt;
    for (int idx = tid; idx < 1024; idx += 544)
        lstS[idx] = list_g[b * 1024 + idx];
    if (tid == 0) scnt = cnt_g[b];
    __syncthreads();
    const int cnt = scnt;
    const int total = cnt * SWEEPS;
    const int P = (total + 3) / 4;

    // coupling tables svd[d-1][m] = C[lst[(m+d)%cnt], lst[m]], d=1..7
    for (int t = tid; t < 7 * cnt; t += 544) {
        int d = t / cnt + 1;
        int m = t - (d - 1) * cnt;
        int mp = m + d; if (mp >= cnt) mp -= cnt;
        sm[F_SVD + (d - 1) * 1024 + m] =
            __ldg(C + (size_t)lstS[mp] * NVARS + lstS[m]);
    }

    // V in registers: warp w owns rows [64w,64w+64), lane l = column l
    unsigned long long v2[32];
    if (dotw) {
#pragma unroll
        for (int p = 0; p < 32; p++) {
            int row = w * 64 + 2 * p;
            v2[p] = pk2(V_g[((size_t)b * 1024 + row) * 32 + l],
                        V_g[((size_t)b * 1024 + row + 1) * 32 + l]);
        }
    }
    __syncthreads();   // svd + lst ready

    // reducer state
    float dvP[4] = {0.f, 0.f, 0.f, 0.f};
    float vold_cur[4];
    if (w == 16) {
#pragma unroll
        for (int s = 0; s < 4; s++)
            vold_cur[s] = VH_g[((size_t)b * 1024 + s) * 32 + l];
    }

    // prologue staging: G1 -> slot1, G2 -> slot2
    if (tid < 256) {
#pragma unroll
        for (int s = 0; s < 4; s++)
            __pipeline_memcpy_async(&sm[F_CBUF + (4 + s) * 1024 + tid * 4],
                                    C + (size_t)lstS[4 + s] * NVARS + tid * 4, 16);
    }
    __pipeline_commit();
    if (tid < 256) {
#pragma unroll
        for (int s = 0; s < 4; s++)
            __pipeline_memcpy_async(&sm[F_CBUF + (8 + s) * 1024 + tid * 4],
                                    C + (size_t)lstS[8 + s] * NVARS + tid * 4, 16);
    }
    __pipeline_commit();

    // prologue dots: G0 from gmem (full init V)
    if (dotw) {
#pragma unroll
        for (int s = 0; s < 4; s++) {
            const ulonglong2* Cp = reinterpret_cast<const ulonglong2*>(
                C + (size_t)lstS[s] * NVARS + w * 64);
            sm[F_PT + 0 * 2048 + s * 512 + w * 32 + l] = dot_row(Cp, v2);
        }
    }
    __pipeline_wait_prior(1);
    __syncthreads();

    int m_prev = 0, m_cur = 0, m_n1 = 4 % cnt, m_stage = 12 % cnt;

    for (int p = 0; p < P; p++) {
        const int rd = p & 1, wr = (p + 1) & 1;

        // stage G_{p+3} into ring slot p%3
        if (tid < 256) {
            int slot = p % 3;
#pragma unroll
            for (int s = 0; s < 4; s++) {
                int mq = m_stage + s; if (mq >= cnt) mq -= cnt;
                __pipeline_memcpy_async(&sm[F_CBUF + (slot * 4 + s) * 1024 + tid * 4],
                                        C + (size_t)lstS[mq] * NVARS + tid * 4, 16);
            }
        }
        __pipeline_commit();

        if (dotw) {
            // apply previous phase's 4 updates
            if (p > 0) {
#pragma unroll
                for (int s = 0; s < 4; s++) {
                    int mp = m_prev + s; if (mp >= cnt) mp -= cnt;
                    int i = lstS[mp];
                    if (w == (i >> 6))
                        insert_elem(v2, i & 63, sm[F_VNB + wr * 128 + s * 32 + l]);
                }
            }
            // dots for G_{p+1} from staged ring slot (p+1)%3
            int slotr = ((p + 1) % 3) * 4;
#pragma unroll
            for (int s = 0; s < 4; s++) {
                const ulonglong2* Cs = reinterpret_cast<const ulonglong2*>(
                    &sm[F_CBUF + (slotr + s) * 1024 + w * 64]);
                sm[F_PT + wr * 2048 + s * 512 + w * 32 + l] = dot_row(Cs, v2);
            }
        } else if (w == 16) {
            // prefetch vold for G_{p+1}
            float vold_nxt[4];
#pragma unroll
            for (int s = 0; s < 4; s++) {
                int mq = m_n1 + s; if (mq >= cnt) mq -= cnt;
                vold_nxt[s] = VH_g[((size_t)b * 1024 + mq) * 32 + l];
            }
            float dv_new[4];
#pragma unroll
            for (int s = 0; s < 4; s++) {
                const float* pr = &sm[F_PT + rd * 2048 + s * 512];
                float t0 = pr[0 * 32 + l],  t1 = pr[1 * 32 + l];
                float t2 = pr[2 * 32 + l],  t3 = pr[3 * 32 + l];
                float t4 = pr[4 * 32 + l],  t5 = pr[5 * 32 + l];
                float t6 = pr[6 * 32 + l],  t7 = pr[7 * 32 + l];
                float t8 = pr[8 * 32 + l],  t9 = pr[9 * 32 + l];
                float ta = pr[10 * 32 + l], tb = pr[11 * 32 + l];
                float tc = pr[12 * 32 + l], td = pr[13 * 32 + l];
                float te = pr[14 * 32 + l], tf = pr[15 * 32 + l];
                float g = (((t0 + t1) + (t2 + t3)) + ((t4 + t5) + (t6 + t7)))
                        + (((t8 + t9) + (ta + tb)) + ((tc + td) + (te + tf)));
                // corrections: previous phase updates (distance d = 4+s-sp)
#pragma unroll
                for (int sp = 0; sp < 4; sp++) {
                    int d = 4 + s - sp;
                    int mq = m_prev + sp; if (mq >= cnt) mq -= cnt;
                    g = fmaf(sm[F_SVD + (d - 1) * 1024 + mq], dvP[sp], g);
                }
                // intra-phase (d = s-sp)
#pragma unroll
                for (int sp = 0; sp < 4; sp++)
                    if (sp < s) {
                        int d = s - sp;
                        int mq = m_cur + sp; if (mq >= cnt) mq -= cnt;
                        g = fmaf(sm[F_SVD + (d - 1) * 1024 + mq], dv_new[sp], g);
                    }
                float ss = warp_sum(g * g);
                ss = fmaxf(ss, 1e-24f);
                float vn = -g * rsqrtf(ss);
                sm[F_VNB + rd * 128 + s * 32 + l] = vn;
                int mq = m_cur + s; if (mq >= cnt) mq -= cnt;
                VH_g[((size_t)b * 1024 + mq) * 32 + l] = vn;
                dv_new[s] = vn - vold_cur[s];
            }
#pragma unroll
            for (int s = 0; s < 4; s++) { dvP[s] = dv_new[s]; vold_cur[s] = vold_nxt[s]; }
        }

        __pipeline_wait_prior(1);
        __syncthreads();

        m_prev = m_cur; m_cur = m_n1;
        m_n1 += 4; if (m_n1 >= cnt) m_n1 -= cnt;
        m_stage += 4; if (m_stage >= cnt) m_stage -= cnt;
    }

    // apply pending last-phase updates (guard stream index < total)
    if (dotw) {
        int baseT = 4 * (P - 1);
        int basem = baseT % cnt;
        int vb = (P - 1) & 1;
#pragma unroll
        for (int s = 0; s < 4; s++) {
            if (baseT + s < total) {
                int mp = basem + s; if (mp >= cnt) mp -= cnt;
                int i = lstS[mp];
                if (w == (i >> 6))
                    insert_elem(v2, i & 63, sm[F_VNB + vb * 128 + s * 32 + l]);
            }
        }
    }

    // ---------------- epilogue: z_out[:, 1:769] ----------------
    if (dotw) {
        float v0l = v0_g[b * 32 + l];
        const float CLO = (float)(-1.0 + 1e-7);
        const float CHI = (float)( 1.0 - 1e-7);
#pragma unroll
        for (int j = 0; j < 64; j++) {
            int n = w * 64 + j;
            if (n >= 1 && n <= NIN) {
                float x, y; up2(v2[j >> 1], x, y);
                float Vv = (j & 1) ? y : x;
                float d = warp_sum(__fmul_rn(Vv, v0l));
                if (l == 0) {
                    int idx = b * NIN + n - 1;
                    float res;
                    if (is_input[idx] != 0) {
                        res = z[idx];
                    } else {
                        float ca = fminf(fmaxf(-d, CLO), CHI);
                        res = acosf(ca) / PI_F;
                    }
                    out[idx] = res;
                }
            }
        }
    }
}

// ---------------- launcher ----------------
extern "C" void kernel_launch(void* const* d_in, const int* in_sizes, int n_in,
                              void* d_out, int out_size) {
    const float* C        = (const float*)d_in[0];
    const float* z        = (const float*)d_in[1];
    const int*   is_input = (const int*)d_in[2];
    float* out = (float*)d_out;

    cudaFuncSetAttribute(mix_kernel,
                         cudaFuncAttributeMaxDynamicSharedMemorySize, SMEM_BYTES);

    v0_kernel<<<BATCH, 32>>>();
    initV_kernel<<<(BATCH * NVARS) / 8, 256>>>(z, is_input);
    freelist_kernel<<<BATCH, 32>>>(is_input);
    vhinit_kernel<<<BATCH, 256>>>();
    mix_kernel<<<BATCH, 544, SMEM_BYTES>>>(C, z, is_input, out);
}